// round 15
// baseline (speedup 1.0000x reference)
#include <cuda_runtime.h>

// SSIM loss, single fused kernel, f32x2-packed separable blur, 4 blur fields.
// Phase 1: full-width remapped aligned float2 loads (924 pair-loads over all
// 256 threads, unrolled for MLP). Phase 3: prefetch-pipelined vertical blur.
// pred/target: (16,3,512,512) f32. Output: scalar f32 = 1 - mean(ssim_map).

#define RAD 5
#define TX 32
#define TY 32
#define PH 42                 // TY + 2*RAD rows
#define SPW2 46               // spt pitch in float2 (368B = 112 mod 128, 16B-mult)
#define HB4P 33               // float4 pitch: 528B = 16 mod 128 -> conflict-free
#define IMG 512
#define NIMG 48
#define TILES 256             // 16 x 16 tiles per image
#define NBLK (TILES * NIMG)   // 12288
#define NPAIR (PH * 22)       // 924 float2-pair loads per block
#define SSIM_C1 1.0e-4f
#define SSIM_C2 9.0e-4f

__device__ float g_bsum[NBLK];
__device__ int g_cnt;         // zero-init; last block resets each run

union F2U { float2 f; unsigned long long u; };

__device__ __forceinline__ unsigned long long pack2(float x, float y) {
    unsigned long long r;
    asm("mov.b64 %0, {%1, %2};" : "=l"(r) : "f"(x), "f"(y));
    return r;
}
__device__ __forceinline__ unsigned long long fma2(unsigned long long a,
                                                   unsigned long long b,
                                                   unsigned long long c) {
    unsigned long long d;
    asm("fma.rn.f32x2 %0, %1, %2, %3;" : "=l"(d) : "l"(a), "l"(b), "l"(c));
    return d;
}
__device__ __forceinline__ unsigned long long mul2(unsigned long long a,
                                                   unsigned long long b) {
    unsigned long long d;
    asm("mul.rn.f32x2 %0, %1, %2;" : "=l"(d) : "l"(a), "l"(b));
    return d;
}

__global__ __launch_bounds__(256, 6)
void ssim_fused(const float* __restrict__ pred,
                const float* __restrict__ target,
                float* __restrict__ out)
{
    // spt[r][i] = (p, t) for image col (x0-1)+i ; halo cols are idx 1..42.
    __shared__ __align__(16) float2 spt[PH][SPW2];
    __shared__ float4 hb[PH][HB4P];           // (h(p), h(t), h(A), h(pt))
    __shared__ float  wsum[4];
    __shared__ double dsum[8];
    __shared__ int    s_last;

    // Normalized 1-D Gaussian, sigma=1.5, size 11 (literals -> FFMA-imm forms).
    const float GWs[11] = {
        0.00102838f, 0.00759876f, 0.03600077f, 0.10936069f, 0.21300553f,
        0.26601173f,
        0.21300553f, 0.10936069f, 0.03600077f, 0.00759876f, 0.00102838f
    };
    unsigned long long GWp[11];
    #pragma unroll
    for (int k = 0; k < 11; k++) GWp[k] = pack2(GWs[k], GWs[k]);

    const int tid  = threadIdx.x;
    const int lane = tid & 31;
    const int wrp  = tid >> 5;

    const int tile_x = blockIdx.x & 15;
    const int tile_y = blockIdx.x >> 4;
    const int bid    = blockIdx.y * TILES + blockIdx.x;
    const float* pb = pred   + (size_t)blockIdx.y * IMG * IMG;
    const float* tb = target + (size_t)blockIdx.y * IMG * IMG;
    const int xm1 = tile_x * TX - RAD - 1;    // even; spt idx 0 = this image col
    const int y0  = tile_y * TY - RAD;

    // ---- Phase 1: 924 float2-pair loads spread over all 256 threads -----
    // idx -> (row = idx/22, pair = idx%22); pair i covers image cols
    // xm1+2i, xm1+2i+1 (both in or both out: xm1 and image edges even).
    const bool interior = (tile_x > 0) && (tile_x < 15) && (tile_y > 0) && (tile_y < 15);
    if (interior) {
        #pragma unroll
        for (int step = 0; step < 4; step++) {
            const int idx = tid + step * 256;
            if (step < 3 || idx < NPAIR) {
                const int r = idx / 22;
                const int p = idx - r * 22;
                const float2* prow = reinterpret_cast<const float2*>(pb + (y0 + r) * IMG + xm1);
                const float2* trow = reinterpret_cast<const float2*>(tb + (y0 + r) * IMG + xm1);
                const float2 pv = __ldg(prow + p);
                const float2 tv = __ldg(trow + p);
                *reinterpret_cast<float4*>(&spt[r][2 * p]) =
                    make_float4(pv.x, tv.x, pv.y, tv.y);
            }
        }
    } else {
        #pragma unroll
        for (int step = 0; step < 4; step++) {
            const int idx = tid + step * 256;
            if (step < 3 || idx < NPAIR) {
                const int r = idx / 22;
                const int p = idx - r * 22;
                const int gy = y0 + r;
                const int gx = xm1 + 2 * p;
                const bool ok = ((unsigned)gy < (unsigned)IMG) &&
                                ((unsigned)gx < (unsigned)IMG);
                float2 pv = make_float2(0.f, 0.f);
                float2 tv = make_float2(0.f, 0.f);
                if (ok) {
                    pv = __ldg(reinterpret_cast<const float2*>(pb + gy * IMG + gx));
                    tv = __ldg(reinterpret_cast<const float2*>(tb + gy * IMG + gx));
                }
                *reinterpret_cast<float4*>(&spt[r][2 * p]) =
                    make_float4(pv.x, tv.x, pv.y, tv.y);
            }
        }
    }
    __syncthreads();

    // ---- Phase 2: horizontal blur, 4 output cols/thread -----------------
    // item = g*42 + r. Output col cx+j needs spt idx cx+j+1..cx+j+11 ->
    // raw window spt[cx .. cx+15] (8x LDS.128).
    #pragma unroll
    for (int half = 0; half < 2; half++) {
        const int it = tid + half * 256;
        if (it < PH * 8) {
            const int g  = it / PH;
            const int r  = it - g * PH;
            const int cx = g * 4;

            float4 raw4[8];
            const float4* rp = reinterpret_cast<const float4*>(&spt[r][cx]);
            #pragma unroll
            for (int q = 0; q < 8; q++) raw4[q] = rp[q];
            const float2* rw = reinterpret_cast<const float2*>(raw4);

            F2U acc12[4], accQ[4];
            #pragma unroll
            for (int j = 0; j < 4; j++) {
                acc12[j].f = make_float2(0.f, 0.f);
                accQ[j].f  = make_float2(0.f, 0.f);
            }

            #pragma unroll
            for (int k = 1; k < 15; k++) {
                F2U e; e.f = rw[k];
                F2U sq; sq.u = mul2(e.u, e.u);          // (p^2, t^2)
                F2U q;
                q.f.x = sq.f.x + sq.f.y;                 // A  = p^2 + t^2
                q.f.y = e.f.x * e.f.y;                   // pt = p * t
                #pragma unroll
                for (int j = 0; j < 4; j++) {
                    const int w = k - 1 - j;
                    if (w >= 0 && w < 11) {
                        acc12[j].u = fma2(GWp[w], e.u, acc12[j].u);
                        accQ[j].u  = fma2(GWp[w], q.u, accQ[j].u);
                    }
                }
            }

            #pragma unroll
            for (int j = 0; j < 4; j++)
                hb[r][cx + j] = make_float4(acc12[j].f.x, acc12[j].f.y,
                                            accQ[j].f.x,  accQ[j].f.y);
        }
    }
    __syncthreads();

    // ---- Phase 3: vertical blur, warps 0-3, 8 rows/thread + SSIM --------
    // 1-deep prefetch pipeline breaks the LDS->FMA dependency per tap.
    if (wrp < 4) {
        const int c  = lane;
        const int yb = wrp * 8;

        F2U a12[8], aQ[8];
        #pragma unroll
        for (int j = 0; j < 8; j++) {
            a12[j].f = make_float2(0.f, 0.f);
            aQ[j].f  = make_float2(0.f, 0.f);
        }

        float4 hcur = hb[yb][c];
        #pragma unroll
        for (int k = 0; k < 18; k++) {
            float4 hnext;
            if (k < 17) hnext = hb[yb + k + 1][c];
            F2U h12; h12.f = make_float2(hcur.x, hcur.y);
            F2U hQ;  hQ.f  = make_float2(hcur.z, hcur.w);
            #pragma unroll
            for (int j = 0; j < 8; j++) {
                const int w = k - j;
                if (w >= 0 && w < 11) {
                    a12[j].u = fma2(GWp[w], h12.u, a12[j].u);
                    aQ[j].u  = fma2(GWp[w], hQ.u,  aQ[j].u);
                }
            }
            hcur = hnext;
        }

        float num[8], den[8];
        #pragma unroll
        for (int j = 0; j < 8; j++) {
            F2U musq; musq.u = mul2(a12[j].u, a12[j].u);    // (mu1^2, mu2^2)
            const float mu12  = a12[j].f.x * a12[j].f.y;     // mu1*mu2
            const float A     = aQ[j].f.x;                   // E[p^2]+E[t^2]
            const float Ept   = aQ[j].f.y;                   // E[pt]
            const float ssum2 = musq.f.x + musq.f.y;         // mu1^2+mu2^2
            const float s12v  = Ept - mu12;                  // sigma12
            num[j] = fmaf(2.f, mu12, SSIM_C1) * fmaf(2.f, s12v, SSIM_C2);
            den[j] = (ssum2 + SSIM_C1) * ((A + SSIM_C2) - ssum2);
        }

        // One division per 4 pixels (den >= ~9e-8; 4-way product stays normal).
        float ssum = 0.f;
        #pragma unroll
        for (int h2 = 0; h2 < 2; h2++) {
            const int b = 4 * h2;
            const float n01 = fmaf(num[b + 0], den[b + 1], num[b + 1] * den[b + 0]);
            const float d01 = den[b + 0] * den[b + 1];
            const float n23 = fmaf(num[b + 2], den[b + 3], num[b + 3] * den[b + 2]);
            const float d23 = den[b + 2] * den[b + 3];
            const float nall = fmaf(n01, d23, n23 * d01);
            const float dall = d01 * d23;
            ssum += __fdividef(nall, dall);
        }

        #pragma unroll
        for (int o = 16; o > 0; o >>= 1)
            ssum += __shfl_xor_sync(0xffffffffu, ssum, o);
        if (lane == 0) wsum[wrp] = ssum;
    }
    __syncthreads();

    // ---- Per-block sum + last-block-done global reduction ---------------
    if (tid == 0) {
        g_bsum[bid] = wsum[0] + wsum[1] + wsum[2] + wsum[3];
        __threadfence();
        const int old = atomicAdd(&g_cnt, 1);
        s_last = (old == NBLK - 1) ? 1 : 0;
    }
    __syncthreads();

    if (s_last) {
        __threadfence();
        double acc0 = 0.0, acc1 = 0.0, acc2 = 0.0, acc3 = 0.0;
        #pragma unroll 1
        for (int i = tid; i < NBLK; i += 1024) {   // 12 iterations, 4-way MLP
            acc0 += (double)g_bsum[i];
            acc1 += (double)g_bsum[i + 256];
            acc2 += (double)g_bsum[i + 512];
            acc3 += (double)g_bsum[i + 768];
        }
        double d = (acc0 + acc1) + (acc2 + acc3);
        #pragma unroll
        for (int o = 16; o > 0; o >>= 1)
            d += __shfl_xor_sync(0xffffffffu, d, o);
        if (lane == 0) dsum[wrp] = d;
        __syncthreads();
        if (tid == 0) {
            double tot = 0.0;
            #pragma unroll
            for (int i = 0; i < 8; i++) tot += dsum[i];
            out[0] = (float)(1.0 - tot / 12582912.0);   // 16*3*512*512
            g_cnt = 0;                                   // reset for next replay
        }
    }
}

extern "C" void kernel_launch(void* const* d_in, const int* in_sizes, int n_in,
                              void* d_out, int out_size)
{
    const float* pred   = (const float*)d_in[0];
    const float* target = (const float*)d_in[1];
    (void)in_sizes; (void)n_in; (void)out_size;

    dim3 grid(TILES, NIMG);   // (256, 48)
    ssim_fused<<<grid, 256>>>(pred, target, (float*)d_out);
}

// round 16
// speedup vs baseline: 1.0133x; 1.0133x over previous
#include <cuda_runtime.h>

// SSIM loss, single fused kernel, f32x2-packed separable blur, 4 blur fields.
// Phase 1: full-width remapped aligned float2 loads (924 pair-loads over all
// 256 threads, unrolled x4 for MLP). Phase 3: plain vertical blur (compiler-
// scheduled). pred/target: (16,3,512,512) f32. Output: 1 - mean(ssim_map).

#define RAD 5
#define TX 32
#define TY 32
#define PH 42                 // TY + 2*RAD rows
#define SPW2 46               // spt pitch in float2 (368B = 112 mod 128, 16B-mult)
#define HB4P 33               // float4 pitch: 528B = 16 mod 128 -> conflict-free
#define IMG 512
#define NIMG 48
#define TILES 256             // 16 x 16 tiles per image
#define NBLK (TILES * NIMG)   // 12288
#define NPAIR (PH * 22)       // 924 float2-pair loads per block
#define SSIM_C1 1.0e-4f
#define SSIM_C2 9.0e-4f

__device__ float g_bsum[NBLK];
__device__ int g_cnt;         // zero-init; last block resets each run

union F2U { float2 f; unsigned long long u; };

__device__ __forceinline__ unsigned long long pack2(float x, float y) {
    unsigned long long r;
    asm("mov.b64 %0, {%1, %2};" : "=l"(r) : "f"(x), "f"(y));
    return r;
}
__device__ __forceinline__ unsigned long long fma2(unsigned long long a,
                                                   unsigned long long b,
                                                   unsigned long long c) {
    unsigned long long d;
    asm("fma.rn.f32x2 %0, %1, %2, %3;" : "=l"(d) : "l"(a), "l"(b), "l"(c));
    return d;
}
__device__ __forceinline__ unsigned long long mul2(unsigned long long a,
                                                   unsigned long long b) {
    unsigned long long d;
    asm("mul.rn.f32x2 %0, %1, %2;" : "=l"(d) : "l"(a), "l"(b));
    return d;
}

__global__ __launch_bounds__(256, 6)
void ssim_fused(const float* __restrict__ pred,
                const float* __restrict__ target,
                float* __restrict__ out)
{
    // spt[r][i] = (p, t) for image col (x0-1)+i ; halo cols are idx 1..42.
    __shared__ __align__(16) float2 spt[PH][SPW2];
    __shared__ float4 hb[PH][HB4P];           // (h(p), h(t), h(A), h(pt))
    __shared__ float  wsum[4];
    __shared__ double dsum[8];
    __shared__ int    s_last;

    // Normalized 1-D Gaussian, sigma=1.5, size 11 (literals -> FFMA-imm forms).
    const float GWs[11] = {
        0.00102838f, 0.00759876f, 0.03600077f, 0.10936069f, 0.21300553f,
        0.26601173f,
        0.21300553f, 0.10936069f, 0.03600077f, 0.00759876f, 0.00102838f
    };
    unsigned long long GWp[11];
    #pragma unroll
    for (int k = 0; k < 11; k++) GWp[k] = pack2(GWs[k], GWs[k]);

    const int tid  = threadIdx.x;
    const int lane = tid & 31;
    const int wrp  = tid >> 5;

    const int tile_x = blockIdx.x & 15;
    const int tile_y = blockIdx.x >> 4;
    const int bid    = blockIdx.y * TILES + blockIdx.x;
    const float* pb = pred   + (size_t)blockIdx.y * IMG * IMG;
    const float* tb = target + (size_t)blockIdx.y * IMG * IMG;
    const int xm1 = tile_x * TX - RAD - 1;    // even; spt idx 0 = this image col
    const int y0  = tile_y * TY - RAD;

    // ---- Phase 1: 924 float2-pair loads spread over all 256 threads -----
    // idx -> (row = idx/22, pair = idx%22); pair i covers image cols
    // xm1+2i, xm1+2i+1 (both in or both out: xm1 and image edges even).
    const bool interior = (tile_x > 0) && (tile_x < 15) && (tile_y > 0) && (tile_y < 15);
    if (interior) {
        #pragma unroll
        for (int step = 0; step < 4; step++) {
            const int idx = tid + step * 256;
            if (step < 3 || idx < NPAIR) {
                const int r = idx / 22;
                const int p = idx - r * 22;
                const float2* prow = reinterpret_cast<const float2*>(pb + (y0 + r) * IMG + xm1);
                const float2* trow = reinterpret_cast<const float2*>(tb + (y0 + r) * IMG + xm1);
                const float2 pv = __ldg(prow + p);
                const float2 tv = __ldg(trow + p);
                *reinterpret_cast<float4*>(&spt[r][2 * p]) =
                    make_float4(pv.x, tv.x, pv.y, tv.y);
            }
        }
    } else {
        #pragma unroll
        for (int step = 0; step < 4; step++) {
            const int idx = tid + step * 256;
            if (step < 3 || idx < NPAIR) {
                const int r = idx / 22;
                const int p = idx - r * 22;
                const int gy = y0 + r;
                const int gx = xm1 + 2 * p;
                const bool ok = ((unsigned)gy < (unsigned)IMG) &&
                                ((unsigned)gx < (unsigned)IMG);
                float2 pv = make_float2(0.f, 0.f);
                float2 tv = make_float2(0.f, 0.f);
                if (ok) {
                    pv = __ldg(reinterpret_cast<const float2*>(pb + gy * IMG + gx));
                    tv = __ldg(reinterpret_cast<const float2*>(tb + gy * IMG + gx));
                }
                *reinterpret_cast<float4*>(&spt[r][2 * p]) =
                    make_float4(pv.x, tv.x, pv.y, tv.y);
            }
        }
    }
    __syncthreads();

    // ---- Phase 2: horizontal blur, 4 output cols/thread -----------------
    // item = g*42 + r. Output col cx+j needs spt idx cx+j+1..cx+j+11 ->
    // raw window spt[cx .. cx+15] (8x LDS.128).
    #pragma unroll
    for (int half = 0; half < 2; half++) {
        const int it = tid + half * 256;
        if (it < PH * 8) {
            const int g  = it / PH;
            const int r  = it - g * PH;
            const int cx = g * 4;

            float4 raw4[8];
            const float4* rp = reinterpret_cast<const float4*>(&spt[r][cx]);
            #pragma unroll
            for (int q = 0; q < 8; q++) raw4[q] = rp[q];
            const float2* rw = reinterpret_cast<const float2*>(raw4);

            F2U acc12[4], accQ[4];
            #pragma unroll
            for (int j = 0; j < 4; j++) {
                acc12[j].f = make_float2(0.f, 0.f);
                accQ[j].f  = make_float2(0.f, 0.f);
            }

            #pragma unroll
            for (int k = 1; k < 15; k++) {
                F2U e; e.f = rw[k];
                F2U sq; sq.u = mul2(e.u, e.u);          // (p^2, t^2)
                F2U q;
                q.f.x = sq.f.x + sq.f.y;                 // A  = p^2 + t^2
                q.f.y = e.f.x * e.f.y;                   // pt = p * t
                #pragma unroll
                for (int j = 0; j < 4; j++) {
                    const int w = k - 1 - j;
                    if (w >= 0 && w < 11) {
                        acc12[j].u = fma2(GWp[w], e.u, acc12[j].u);
                        accQ[j].u  = fma2(GWp[w], q.u, accQ[j].u);
                    }
                }
            }

            #pragma unroll
            for (int j = 0; j < 4; j++)
                hb[r][cx + j] = make_float4(acc12[j].f.x, acc12[j].f.y,
                                            accQ[j].f.x,  accQ[j].f.y);
        }
    }
    __syncthreads();

    // ---- Phase 3: vertical blur, warps 0-3, 8 rows/thread + SSIM --------
    if (wrp < 4) {
        const int c  = lane;
        const int yb = wrp * 8;

        F2U a12[8], aQ[8];
        #pragma unroll
        for (int j = 0; j < 8; j++) {
            a12[j].f = make_float2(0.f, 0.f);
            aQ[j].f  = make_float2(0.f, 0.f);
        }

        #pragma unroll
        for (int k = 0; k < 18; k++) {
            const float4 h = hb[yb + k][c];
            F2U h12; h12.f = make_float2(h.x, h.y);
            F2U hQ;  hQ.f  = make_float2(h.z, h.w);
            #pragma unroll
            for (int j = 0; j < 8; j++) {
                const int w = k - j;
                if (w >= 0 && w < 11) {
                    a12[j].u = fma2(GWp[w], h12.u, a12[j].u);
                    aQ[j].u  = fma2(GWp[w], hQ.u,  aQ[j].u);
                }
            }
        }

        float num[8], den[8];
        #pragma unroll
        for (int j = 0; j < 8; j++) {
            F2U musq; musq.u = mul2(a12[j].u, a12[j].u);    // (mu1^2, mu2^2)
            const float mu12  = a12[j].f.x * a12[j].f.y;     // mu1*mu2
            const float A     = aQ[j].f.x;                   // E[p^2]+E[t^2]
            const float Ept   = aQ[j].f.y;                   // E[pt]
            const float ssum2 = musq.f.x + musq.f.y;         // mu1^2+mu2^2
            const float s12v  = Ept - mu12;                  // sigma12
            num[j] = fmaf(2.f, mu12, SSIM_C1) * fmaf(2.f, s12v, SSIM_C2);
            den[j] = (ssum2 + SSIM_C1) * ((A + SSIM_C2) - ssum2);
        }

        // One division per 4 pixels (den >= ~9e-8; 4-way product stays normal).
        float ssum = 0.f;
        #pragma unroll
        for (int h2 = 0; h2 < 2; h2++) {
            const int b = 4 * h2;
            const float n01 = fmaf(num[b + 0], den[b + 1], num[b + 1] * den[b + 0]);
            const float d01 = den[b + 0] * den[b + 1];
            const float n23 = fmaf(num[b + 2], den[b + 3], num[b + 3] * den[b + 2]);
            const float d23 = den[b + 2] * den[b + 3];
            const float nall = fmaf(n01, d23, n23 * d01);
            const float dall = d01 * d23;
            ssum += __fdividef(nall, dall);
        }

        #pragma unroll
        for (int o = 16; o > 0; o >>= 1)
            ssum += __shfl_xor_sync(0xffffffffu, ssum, o);
        if (lane == 0) wsum[wrp] = ssum;
    }
    __syncthreads();

    // ---- Per-block sum + last-block-done global reduction ---------------
    if (tid == 0) {
        g_bsum[bid] = wsum[0] + wsum[1] + wsum[2] + wsum[3];
        __threadfence();
        const int old = atomicAdd(&g_cnt, 1);
        s_last = (old == NBLK - 1) ? 1 : 0;
    }
    __syncthreads();

    if (s_last) {
        __threadfence();
        double acc0 = 0.0, acc1 = 0.0, acc2 = 0.0, acc3 = 0.0;
        #pragma unroll 1
        for (int i = tid; i < NBLK; i += 1024) {   // 12 iterations, 4-way MLP
            acc0 += (double)g_bsum[i];
            acc1 += (double)g_bsum[i + 256];
            acc2 += (double)g_bsum[i + 512];
            acc3 += (double)g_bsum[i + 768];
        }
        double d = (acc0 + acc1) + (acc2 + acc3);
        #pragma unroll
        for (int o = 16; o > 0; o >>= 1)
            d += __shfl_xor_sync(0xffffffffu, d, o);
        if (lane == 0) dsum[wrp] = d;
        __syncthreads();
        if (tid == 0) {
            double tot = 0.0;
            #pragma unroll
            for (int i = 0; i < 8; i++) tot += dsum[i];
            out[0] = (float)(1.0 - tot / 12582912.0);   // 16*3*512*512
            g_cnt = 0;                                   // reset for next replay
        }
    }
}

extern "C" void kernel_launch(void* const* d_in, const int* in_sizes, int n_in,
                              void* d_out, int out_size)
{
    const float* pred   = (const float*)d_in[0];
    const float* target = (const float*)d_in[1];
    (void)in_sizes; (void)n_in; (void)out_size;

    dim3 grid(TILES, NIMG);   // (256, 48)
    ssim_fused<<<grid, 256>>>(pred, target, (float*)d_out);
}

// round 17
// speedup vs baseline: 1.0509x; 1.0371x over previous
#include <cuda_runtime.h>

// SSIM loss, single fused kernel, f32x2-packed separable blur, 4 blur fields.
// Phase 1: full-width remapped aligned float2 loads. Phase 2: 4-col hpass.
// Phase 3: vertical blur + SSIM (1 division per 4 pixels). Last-block global
// reduction with 12-way MLP. pred/target: (16,3,512,512) f32.
// Output: scalar f32 = 1 - mean(ssim_map).

#define RAD 5
#define TX 32
#define TY 32
#define PH 42                 // TY + 2*RAD rows
#define SPW2 46               // spt pitch in float2 (368B = 112 mod 128, 16B-mult)
#define HB4P 33               // float4 pitch: 528B = 16 mod 128 -> conflict-free
#define IMG 512
#define NIMG 48
#define TILES 256             // 16 x 16 tiles per image
#define NBLK (TILES * NIMG)   // 12288
#define NPAIR (PH * 22)       // 924 float2-pair loads per block
#define SSIM_C1 1.0e-4f
#define SSIM_C2 9.0e-4f

__device__ float g_bsum[NBLK];
__device__ int g_cnt;         // zero-init; last block resets each run

union F2U { float2 f; unsigned long long u; };

__device__ __forceinline__ unsigned long long pack2(float x, float y) {
    unsigned long long r;
    asm("mov.b64 %0, {%1, %2};" : "=l"(r) : "f"(x), "f"(y));
    return r;
}
__device__ __forceinline__ unsigned long long fma2(unsigned long long a,
                                                   unsigned long long b,
                                                   unsigned long long c) {
    unsigned long long d;
    asm("fma.rn.f32x2 %0, %1, %2, %3;" : "=l"(d) : "l"(a), "l"(b), "l"(c));
    return d;
}
__device__ __forceinline__ unsigned long long mul2(unsigned long long a,
                                                   unsigned long long b) {
    unsigned long long d;
    asm("mul.rn.f32x2 %0, %1, %2;" : "=l"(d) : "l"(a), "l"(b));
    return d;
}

__global__ __launch_bounds__(256, 6)
void ssim_fused(const float* __restrict__ pred,
                const float* __restrict__ target,
                float* __restrict__ out)
{
    // spt[r][i] = (p, t) for image col (x0-1)+i ; halo cols are idx 1..42.
    __shared__ __align__(16) float2 spt[PH][SPW2];
    __shared__ float4 hb[PH][HB4P];           // (h(p), h(t), h(A), h(pt))
    __shared__ float  wsum[4];
    __shared__ double dsum[8];
    __shared__ int    s_last;

    // Normalized 1-D Gaussian, sigma=1.5, size 11 (literals -> FFMA-imm forms).
    const float GWs[11] = {
        0.00102838f, 0.00759876f, 0.03600077f, 0.10936069f, 0.21300553f,
        0.26601173f,
        0.21300553f, 0.10936069f, 0.03600077f, 0.00759876f, 0.00102838f
    };
    unsigned long long GWp[11];
    #pragma unroll
    for (int k = 0; k < 11; k++) GWp[k] = pack2(GWs[k], GWs[k]);

    const int tid  = threadIdx.x;
    const int lane = tid & 31;
    const int wrp  = tid >> 5;

    const int tile_x = blockIdx.x & 15;
    const int tile_y = blockIdx.x >> 4;
    const int bid    = blockIdx.y * TILES + blockIdx.x;
    const float* pb = pred   + (size_t)blockIdx.y * IMG * IMG;
    const float* tb = target + (size_t)blockIdx.y * IMG * IMG;
    const int xm1 = tile_x * TX - RAD - 1;    // even; spt idx 0 = this image col
    const int y0  = tile_y * TY - RAD;

    // ---- Phase 1: 924 float2-pair loads spread over all 256 threads -----
    // idx -> (row = idx/22, pair = idx%22); pair i covers image cols
    // xm1+2i, xm1+2i+1 (both in or both out: xm1 and image edges even).
    const bool interior = (tile_x > 0) && (tile_x < 15) && (tile_y > 0) && (tile_y < 15);
    if (interior) {
        #pragma unroll
        for (int step = 0; step < 4; step++) {
            const int idx = tid + step * 256;
            if (step < 3 || idx < NPAIR) {
                const int r = idx / 22;
                const int p = idx - r * 22;
                const float2* prow = reinterpret_cast<const float2*>(pb + (y0 + r) * IMG + xm1);
                const float2* trow = reinterpret_cast<const float2*>(tb + (y0 + r) * IMG + xm1);
                const float2 pv = __ldg(prow + p);
                const float2 tv = __ldg(trow + p);
                *reinterpret_cast<float4*>(&spt[r][2 * p]) =
                    make_float4(pv.x, tv.x, pv.y, tv.y);
            }
        }
    } else {
        #pragma unroll
        for (int step = 0; step < 4; step++) {
            const int idx = tid + step * 256;
            if (step < 3 || idx < NPAIR) {
                const int r = idx / 22;
                const int p = idx - r * 22;
                const int gy = y0 + r;
                const int gx = xm1 + 2 * p;
                const bool ok = ((unsigned)gy < (unsigned)IMG) &&
                                ((unsigned)gx < (unsigned)IMG);
                float2 pv = make_float2(0.f, 0.f);
                float2 tv = make_float2(0.f, 0.f);
                if (ok) {
                    pv = __ldg(reinterpret_cast<const float2*>(pb + gy * IMG + gx));
                    tv = __ldg(reinterpret_cast<const float2*>(tb + gy * IMG + gx));
                }
                *reinterpret_cast<float4*>(&spt[r][2 * p]) =
                    make_float4(pv.x, tv.x, pv.y, tv.y);
            }
        }
    }
    __syncthreads();

    // ---- Phase 2: horizontal blur, 4 output cols/thread -----------------
    // item = g*42 + r. Output col cx+j needs spt idx cx+j+1..cx+j+11 ->
    // raw window spt[cx .. cx+15] (8x LDS.128).
    #pragma unroll
    for (int half = 0; half < 2; half++) {
        const int it = tid + half * 256;
        if (it < PH * 8) {
            const int g  = it / PH;
            const int r  = it - g * PH;
            const int cx = g * 4;

            float4 raw4[8];
            const float4* rp = reinterpret_cast<const float4*>(&spt[r][cx]);
            #pragma unroll
            for (int q = 0; q < 8; q++) raw4[q] = rp[q];
            const float2* rw = reinterpret_cast<const float2*>(raw4);

            F2U acc12[4], accQ[4];
            #pragma unroll
            for (int j = 0; j < 4; j++) {
                acc12[j].f = make_float2(0.f, 0.f);
                accQ[j].f  = make_float2(0.f, 0.f);
            }

            #pragma unroll
            for (int k = 1; k < 15; k++) {
                F2U e; e.f = rw[k];
                F2U sq; sq.u = mul2(e.u, e.u);          // (p^2, t^2)
                F2U q;
                q.f.x = sq.f.x + sq.f.y;                 // A  = p^2 + t^2
                q.f.y = e.f.x * e.f.y;                   // pt = p * t
                #pragma unroll
                for (int j = 0; j < 4; j++) {
                    const int w = k - 1 - j;
                    if (w >= 0 && w < 11) {
                        acc12[j].u = fma2(GWp[w], e.u, acc12[j].u);
                        accQ[j].u  = fma2(GWp[w], q.u, accQ[j].u);
                    }
                }
            }

            #pragma unroll
            for (int j = 0; j < 4; j++)
                hb[r][cx + j] = make_float4(acc12[j].f.x, acc12[j].f.y,
                                            accQ[j].f.x,  accQ[j].f.y);
        }
    }
    __syncthreads();

    // ---- Phase 3: vertical blur, warps 0-3, 8 rows/thread + SSIM --------
    if (wrp < 4) {
        const int c  = lane;
        const int yb = wrp * 8;

        F2U a12[8], aQ[8];
        #pragma unroll
        for (int j = 0; j < 8; j++) {
            a12[j].f = make_float2(0.f, 0.f);
            aQ[j].f  = make_float2(0.f, 0.f);
        }

        #pragma unroll
        for (int k = 0; k < 18; k++) {
            const float4 h = hb[yb + k][c];
            F2U h12; h12.f = make_float2(h.x, h.y);
            F2U hQ;  hQ.f  = make_float2(h.z, h.w);
            #pragma unroll
            for (int j = 0; j < 8; j++) {
                const int w = k - j;
                if (w >= 0 && w < 11) {
                    a12[j].u = fma2(GWp[w], h12.u, a12[j].u);
                    aQ[j].u  = fma2(GWp[w], hQ.u,  aQ[j].u);
                }
            }
        }

        float num[8], den[8];
        #pragma unroll
        for (int j = 0; j < 8; j++) {
            F2U musq; musq.u = mul2(a12[j].u, a12[j].u);    // (mu1^2, mu2^2)
            const float mu12  = a12[j].f.x * a12[j].f.y;     // mu1*mu2
            const float A     = aQ[j].f.x;                   // E[p^2]+E[t^2]
            const float Ept   = aQ[j].f.y;                   // E[pt]
            const float ssum2 = musq.f.x + musq.f.y;         // mu1^2+mu2^2
            const float s12v  = Ept - mu12;                  // sigma12
            num[j] = fmaf(2.f, mu12, SSIM_C1) * fmaf(2.f, s12v, SSIM_C2);
            den[j] = (ssum2 + SSIM_C1) * ((A + SSIM_C2) - ssum2);
        }

        // One division per 4 pixels (den >= ~9e-8; 4-way product stays normal).
        float ssum = 0.f;
        #pragma unroll
        for (int h2 = 0; h2 < 2; h2++) {
            const int b = 4 * h2;
            const float n01 = fmaf(num[b + 0], den[b + 1], num[b + 1] * den[b + 0]);
            const float d01 = den[b + 0] * den[b + 1];
            const float n23 = fmaf(num[b + 2], den[b + 3], num[b + 3] * den[b + 2]);
            const float d23 = den[b + 2] * den[b + 3];
            const float nall = fmaf(n01, d23, n23 * d01);
            const float dall = d01 * d23;
            ssum += __fdividef(nall, dall);
        }

        #pragma unroll
        for (int o = 16; o > 0; o >>= 1)
            ssum += __shfl_xor_sync(0xffffffffu, ssum, o);
        if (lane == 0) wsum[wrp] = ssum;
    }
    __syncthreads();

    // ---- Per-block sum + last-block-done global reduction ---------------
    if (tid == 0) {
        g_bsum[bid] = wsum[0] + wsum[1] + wsum[2] + wsum[3];
        __threadfence();
        const int old = atomicAdd(&g_cnt, 1);
        s_last = (old == NBLK - 1) ? 1 : 0;
    }
    __syncthreads();

    if (s_last) {
        __threadfence();
        // 12288 values over 256 threads: 4 batches x 12 independent loads.
        double acc[12];
        #pragma unroll
        for (int j = 0; j < 12; j++) acc[j] = 0.0;
        #pragma unroll
        for (int step = 0; step < 4; step++) {
            #pragma unroll
            for (int j = 0; j < 12; j++)
                acc[j] += (double)g_bsum[tid + 256 * (j + 12 * step)];
        }
        double d = ((acc[0] + acc[1]) + (acc[2] + acc[3]))
                 + ((acc[4] + acc[5]) + (acc[6] + acc[7]))
                 + ((acc[8] + acc[9]) + (acc[10] + acc[11]));
        #pragma unroll
        for (int o = 16; o > 0; o >>= 1)
            d += __shfl_xor_sync(0xffffffffu, d, o);
        if (lane == 0) dsum[wrp] = d;
        __syncthreads();
        if (tid == 0) {
            double tot = 0.0;
            #pragma unroll
            for (int i = 0; i < 8; i++) tot += dsum[i];
            out[0] = (float)(1.0 - tot / 12582912.0);   // 16*3*512*512
            g_cnt = 0;                                   // reset for next replay
        }
    }
}

extern "C" void kernel_launch(void* const* d_in, const int* in_sizes, int n_in,
                              void* d_out, int out_size)
{
    const float* pred   = (const float*)d_in[0];
    const float* target = (const float*)d_in[1];
    (void)in_sizes; (void)n_in; (void)out_size;

    dim3 grid(TILES, NIMG);   // (256, 48)
    ssim_fused<<<grid, 256>>>(pred, target, (float*)d_out);
}